// round 15
// baseline (speedup 1.0000x reference)
#include <cuda_runtime.h>
#include <cuda_fp16.h>
#include <cstdint>

// Problem constants
#define Bq 4
#define Lq 8192
#define Dq 512
#define Hq 1024
#define Mq (Bq*Lq)        // 32768
#define NCHUNK 128
#define CLEN 64

// ---------------------------------------------------------------------------
// Scratch (device globals; allocation is forbidden)
// ---------------------------------------------------------------------------
__device__ __half2 g_cz[(size_t)Mq*Hq];     // (c, zg) packed
__device__ float g_A [Bq*NCHUNK*Hq];
__device__ float g_Bc[Bq*NCHUNK*Hq];
__device__ float g_hs[Bq*NCHUNK*Hq];
__device__ __half g_xh[(size_t)Mq*Dq];
__device__ __half g_wih[2*Hq*Dq];
__device__ __half g_woh[Dq*Hq];
__device__ __half g_hh[(size_t)Mq*Hq];

// ---------------------------------------------------------------------------
// PTX helpers
// ---------------------------------------------------------------------------
__device__ __forceinline__ uint32_t s2u(const void* p) {
    uint32_t a;
    asm("{ .reg .u64 t; cvta.to.shared.u64 t, %1; cvt.u32.u64 %0, t; }"
        : "=r"(a) : "l"(p));
    return a;
}
#define LDSM_X4(r0,r1,r2,r3,addr) \
    asm volatile("ldmatrix.sync.aligned.m8n8.x4.shared.b16 {%0,%1,%2,%3}, [%4];" \
        : "=r"(r0),"=r"(r1),"=r"(r2),"=r"(r3) : "r"(addr))

#define MMA_F16(c0,c1,c2,c3,a0,a1,a2,a3,b0,b1) \
    asm volatile("mma.sync.aligned.m16n8k16.row.col.f32.f16.f16.f32 " \
        "{%0,%1,%2,%3},{%4,%5,%6,%7},{%8,%9},{%0,%1,%2,%3};" \
        : "+f"(c0),"+f"(c1),"+f"(c2),"+f"(c3) \
        : "r"(a0),"r"(a1),"r"(a2),"r"(a3),"r"(b0),"r"(b1))

__device__ __forceinline__ void cpa16(uint32_t dst, const void* src) {
    asm volatile("cp.async.cg.shared.global [%0], [%1], 16;"
                 :: "r"(dst), "l"(src));
}
#define CP_COMMIT() asm volatile("cp.async.commit_group;")
#define CP_WAIT2()  asm volatile("cp.async.wait_group 2;")
#define CP_WAIT1()  asm volatile("cp.async.wait_group 1;")
#define CP_WAIT0()  asm volatile("cp.async.wait_group 0;")

__device__ __forceinline__ void pipe_wait(int rem)
{
    if (rem >= 2)      { CP_WAIT2(); }
    else if (rem == 1) { CP_WAIT1(); }
    else               { CP_WAIT0(); }
}

// smem: BK=32, LDK=40 (80B rows, conflict-free ldmatrix).
// Stage: A 256 rows + B 128 rows.
#define LDK 40
#define ROWB (LDK*2)                   // 80 bytes per row
#define TILE_A (256*ROWB)              // 20480
#define TILE_B (128*ROWB)              // 10240
#define OFF_A 0
#define OFF_B TILE_A
#define STAGE_B (TILE_A + TILE_B)      // 30720
#define STAGES 4
#define SMEM_TOTAL (STAGES*STAGE_B)    // 122880 (1 CTA/SM)

// ---------------------------------------------------------------------------
// convert: f32 -> fp16
// ---------------------------------------------------------------------------
__device__ __forceinline__ unsigned short hfu(__half h) {
    return *reinterpret_cast<unsigned short*>(&h);
}
__global__ void conv_f16(const float* __restrict__ s,
                         __half* __restrict__ hi, int n4)
{
    int i = blockIdx.x * blockDim.x + threadIdx.x;
    if (i >= n4) return;
    float4 v = ((const float4*)s)[i];
    __half hx = __float2half_rn(v.x), hy = __float2half_rn(v.y);
    __half hz = __float2half_rn(v.z), hw = __float2half_rn(v.w);
    uint2 H;
    H.x = (unsigned)hfu(hx) | ((unsigned)hfu(hy) << 16);
    H.y = (unsigned)hfu(hz) | ((unsigned)hfu(hw) << 16);
    ((uint2*)hi)[i] = H;
}

// ---------------------------------------------------------------------------
// MMA consume for one BK=32 stage. Warp tile 64m x 64n (4 m-frags x 8 n-frags).
// ---------------------------------------------------------------------------
__device__ __forceinline__ void mma_stage(uint32_t bb, int lane, int wm, int wn,
                                          float acc[4][8][4])
{
    #pragma unroll
    for (int ks = 0; ks < 2; ks++) {
        int kk = ks * 16;
        unsigned aH[4][4];
        {
            int ar = lane & 15;
            int ac = kk + 8 * (lane >> 4);
            #pragma unroll
            for (int mi = 0; mi < 4; mi++) {
                unsigned off = (wm + mi*16 + ar) * ROWB + ac * 2;
                LDSM_X4(aH[mi][0],aH[mi][1],aH[mi][2],aH[mi][3], bb + OFF_A + off);
            }
        }
        unsigned bH[8][2];
        {
            int r  = lane & 7;
            int kc = kk + ((lane >> 3) & 1) * 8;
            int n8 = (lane >> 4) ? 8 : 0;
            #pragma unroll
            for (int p = 0; p < 4; p++) {
                unsigned off = (wn + p*16 + n8 + r) * ROWB + kc * 2;
                LDSM_X4(bH[2*p][0],bH[2*p][1],bH[2*p+1][0],bH[2*p+1][1],
                        bb + OFF_B + off);
            }
        }
        #pragma unroll
        for (int mi = 0; mi < 4; mi++)
            #pragma unroll
            for (int ni = 0; ni < 8; ni++) {
                float* c = acc[mi][ni];
                MMA_F16(c[0],c[1],c[2],c[3],
                        aH[mi][0],aH[mi][1],aH[mi][2],aH[mi][3],
                        bH[ni][0],bH[ni][1]);
            }
    }
}

// ---------------------------------------------------------------------------
// K1: gemm1 (x @ W_in^T) + activation epilogue. Block 256m x 128col, K=512.
// Col j -> channel ch0+(j>>1); j&1: 0=hidden W row, 1=gate W row.
// Warps: 4 m-groups x 2 n-groups, warp tile 64x64. 4-stage, 1 sync/iter.
// ---------------------------------------------------------------------------
__global__ __launch_bounds__(256, 1)
void gemm1_tc(const float* __restrict__ bin)
{
    extern __shared__ char smem[];
    uint32_t su = s2u(smem);
    const int tid = threadIdx.x;
    const int lane = tid & 31;
    const int warp = tid >> 5;
    const int wm = (warp >> 1) * 64;
    const int wn = (warp & 1) * 64;
    const int m0 = blockIdx.x * 256;
    const int ch0 = blockIdx.y * 64;
    const int NC = Dq / 32;   // 16

    float acc[4][8][4];
    #pragma unroll
    for (int i = 0; i < 4; i++)
        #pragma unroll
        for (int j = 0; j < 8; j++)
            #pragma unroll
            for (int q = 0; q < 4; q++) acc[i][j][q] = 0.f;

    auto stage = [&](int c) {
        uint32_t bb = su + (c % STAGES) * STAGE_B;
        int k0 = c * 32;
        // A: 256 rows x 32 cols
        #pragma unroll
        for (int i = 0; i < 4; i++) {
            int id = tid + 256 * i;
            int row = id >> 2, c8 = id & 3;
            uint32_t off = (uint32_t)(row * ROWB + c8 * 16);
            size_t ai = (size_t)(m0 + row) * Dq + k0 + c8 * 8;
            cpa16(bb + OFF_A + off, g_xh + ai);
        }
        // B: 128 rows (interleaved hidden/gate)
        #pragma unroll
        for (int i = 0; i < 2; i++) {
            int id = tid + 256 * i;
            int row = id >> 2, c8 = id & 3;
            uint32_t off = (uint32_t)(row * ROWB + c8 * 16);
            int wrow = (row & 1) ? (Hq + ch0 + (row >> 1)) : (ch0 + (row >> 1));
            size_t bi = (size_t)wrow * Dq + k0 + c8 * 8;
            cpa16(bb + OFF_B + off, g_wih + bi);
        }
        CP_COMMIT();
    };

    stage(0); stage(1); stage(2);
    for (int c = 0; c < NC; c++) {
        pipe_wait(NC - 1 - c < STAGES-2 ? NC - 1 - c : STAGES-2);
        __syncthreads();
        if (c + 3 < NC) stage(c + 3);
        mma_stage(su + (c % STAGES) * STAGE_B, lane, wm, wn, acc);
    }

    // epilogue: activations -> packed half2 (c, zg)
    #pragma unroll
    for (int ni = 0; ni < 8; ni++) {
        int nloc = wn + ni*8 + 2*(lane & 3);
        int ch = ch0 + (nloc >> 1);
        float bh = bin[ch], bg = bin[Hq + ch];
        #pragma unroll
        for (int mi = 0; mi < 4; mi++) {
            float* c = acc[mi][ni];
            #pragma unroll
            for (int half = 0; half < 2; half++) {
                int row = m0 + wm + mi*16 + (lane >> 2) + half*8;
                float hid = c[2*half]   + bh;
                float gat = c[2*half+1] + bg;
                float z  = 1.f/(1.f + __expf(-gat));
                float cc = 1.f - z;
                float gt = (hid >= 0.f) ? (hid + 0.5f)
                                        : (1.f/(1.f + __expf(-hid)));
                g_cz[(size_t)row*Hq + ch] = __floats2half2_rn(cc, z * gt);
            }
        }
    }
}

// ---------------------------------------------------------------------------
// K2-K4: chunked scan (reads packed half2)
// ---------------------------------------------------------------------------
__global__ void scan_chunks()
{
    int h = blockIdx.x*256 + threadIdx.x;
    int chunk = blockIdx.y, b = blockIdx.z;
    size_t base = ((size_t)b*Lq + (size_t)chunk*CLEN)*Hq + h;
    float A = 1.f, Bv = 0.f;
    #pragma unroll 8
    for (int t = 0; t < CLEN; t++) {
        float2 v = __half22float2(g_cz[base]);
        Bv = v.x*Bv + v.y;
        A *= v.x;
        base += Hq;
    }
    size_t o = ((size_t)b*NCHUNK + chunk)*Hq + h;
    g_A[o] = A; g_Bc[o] = Bv;
}

__global__ void scan_tops()
{
    int g = blockIdx.x*256 + threadIdx.x;
    int b = g >> 10, hh = g & 1023;
    float hs = 0.f;
    size_t o = ((size_t)b*NCHUNK)*Hq + hh;
    for (int i = 0; i < NCHUNK; i++) {
        g_hs[o] = hs;
        hs = g_A[o]*hs + g_Bc[o];
        o += Hq;
    }
}

__global__ void scan_apply()
{
    int h = blockIdx.x*256 + threadIdx.x;
    int chunk = blockIdx.y, b = blockIdx.z;
    float hs = g_hs[((size_t)b*NCHUNK + chunk)*Hq + h];
    size_t base = ((size_t)b*Lq + (size_t)chunk*CLEN)*Hq + h;
    #pragma unroll 8
    for (int t = 0; t < CLEN; t++) {
        float2 v = __half22float2(g_cz[base]);
        hs = v.x*hs + v.y;
        g_hh[base] = __float2half_rn(hs);
        base += Hq;
    }
}

// ---------------------------------------------------------------------------
// K5: gemm2 (h @ W_out^T + b_out). Block 256m x 128n, K=1024.
// ---------------------------------------------------------------------------
__global__ __launch_bounds__(256, 1)
void gemm2_tc(const float* __restrict__ bout, float* __restrict__ Out)
{
    extern __shared__ char smem[];
    uint32_t su = s2u(smem);
    const int tid = threadIdx.x;
    const int lane = tid & 31;
    const int warp = tid >> 5;
    const int wm = (warp >> 1) * 64;
    const int wn = (warp & 1) * 64;
    const int m0 = blockIdx.x * 256;
    const int n0 = blockIdx.y * 128;
    const int NC = Hq / 32;   // 32

    float acc[4][8][4];
    #pragma unroll
    for (int i = 0; i < 4; i++)
        #pragma unroll
        for (int j = 0; j < 8; j++)
            #pragma unroll
            for (int q = 0; q < 4; q++) acc[i][j][q] = 0.f;

    auto stage = [&](int c) {
        uint32_t bb = su + (c % STAGES) * STAGE_B;
        int k0 = c * 32;
        #pragma unroll
        for (int i = 0; i < 4; i++) {
            int id = tid + 256 * i;
            int row = id >> 2, c8 = id & 3;
            uint32_t off = (uint32_t)(row * ROWB + c8 * 16);
            size_t ai = (size_t)(m0 + row) * Hq + k0 + c8 * 8;
            cpa16(bb + OFF_A + off, g_hh + ai);
        }
        #pragma unroll
        for (int i = 0; i < 2; i++) {
            int id = tid + 256 * i;
            int row = id >> 2, c8 = id & 3;
            uint32_t off = (uint32_t)(row * ROWB + c8 * 16);
            size_t bi = (size_t)(n0 + row) * Hq + k0 + c8 * 8;
            cpa16(bb + OFF_B + off, g_woh + bi);
        }
        CP_COMMIT();
    };

    stage(0); stage(1); stage(2);
    for (int c = 0; c < NC; c++) {
        pipe_wait(NC - 1 - c < STAGES-2 ? NC - 1 - c : STAGES-2);
        __syncthreads();
        if (c + 3 < NC) stage(c + 3);
        mma_stage(su + (c % STAGES) * STAGE_B, lane, wm, wn, acc);
    }

    #pragma unroll
    for (int ni = 0; ni < 8; ni++) {
        int nd = n0 + wn + ni*8 + 2*(lane & 3);
        float b0 = bout[nd], b1 = bout[nd+1];
        #pragma unroll
        for (int mi = 0; mi < 4; mi++) {
            float* c = acc[mi][ni];
            #pragma unroll
            for (int half = 0; half < 2; half++) {
                int row = m0 + wm + mi*16 + (lane >> 2) + half*8;
                float2 o;
                o.x = c[2*half]   + b0;
                o.y = c[2*half+1] + b1;
                *(float2*)(Out + (size_t)row*Dq + nd) = o;
            }
        }
    }
}

// ---------------------------------------------------------------------------
extern "C" void kernel_launch(void* const* d_in, const int* in_sizes, int n_in,
                              void* d_out, int out_size)
{
    const float *x = nullptr, *win = nullptr, *bin = nullptr,
                *wout = nullptr, *bout = nullptr;
    for (int i = 0; i < n_in; i++) {
        switch (in_sizes[i]) {
            case Bq*Lq*Dq: x    = (const float*)d_in[i]; break;
            case 2*Hq*Dq:  win  = (const float*)d_in[i]; break;
            case 2*Hq:     bin  = (const float*)d_in[i]; break;
            case Dq*Hq:    wout = (const float*)d_in[i]; break;
            case Dq:       bout = (const float*)d_in[i]; break;
        }
    }
    float* out = (float*)d_out;

    static bool attr_done = false;
    if (!attr_done) {
        cudaFuncSetAttribute(gemm1_tc, cudaFuncAttributeMaxDynamicSharedMemorySize, SMEM_TOTAL);
        cudaFuncSetAttribute(gemm2_tc, cudaFuncAttributeMaxDynamicSharedMemorySize, SMEM_TOTAL);
        attr_done = true;
    }

    __half *xh, *wih, *woh;
    cudaGetSymbolAddress((void**)&xh,  g_xh);
    cudaGetSymbolAddress((void**)&wih, g_wih);
    cudaGetSymbolAddress((void**)&woh, g_woh);

    conv_f16<<<(Mq*Dq/4 + 255)/256, 256>>>(x, xh, Mq*Dq/4);
    conv_f16<<<(2*Hq*Dq/4 + 255)/256, 256>>>(win, wih, 2*Hq*Dq/4);
    conv_f16<<<(Dq*Hq/4 + 255)/256, 256>>>(wout, woh, Dq*Hq/4);

    gemm1_tc   <<<dim3(Mq/256, 2*Hq/128), 256, SMEM_TOTAL>>>(bin);
    scan_chunks<<<dim3(Hq/256, NCHUNK, Bq), 256>>>();
    scan_tops  <<<16, 256>>>();
    scan_apply <<<dim3(Hq/256, NCHUNK, Bq), 256>>>();
    gemm2_tc   <<<dim3(Mq/256, Dq/128), 256, SMEM_TOTAL>>>(bout, out);
}

// round 17
// speedup vs baseline: 1.3176x; 1.3176x over previous
#include <cuda_runtime.h>
#include <cuda_fp16.h>
#include <cstdint>

// Problem constants
#define Bq 4
#define Lq 8192
#define Dq 512
#define Hq 1024
#define Mq (Bq*Lq)        // 32768
#define NCHUNK 128
#define CLEN 64

// ---------------------------------------------------------------------------
// Scratch (device globals; allocation is forbidden)
// ---------------------------------------------------------------------------
__device__ __half2 g_cz[(size_t)Mq*Hq];     // (c, zg) packed
__device__ float g_A [Bq*NCHUNK*Hq];
__device__ float g_Bc[Bq*NCHUNK*Hq];
__device__ float g_hs[Bq*NCHUNK*Hq];
__device__ __half g_xh[(size_t)Mq*Dq];
__device__ __half g_wih[2*Hq*Dq];
__device__ __half g_woh[Dq*Hq];
__device__ __half g_hh[(size_t)Mq*Hq];

// ---------------------------------------------------------------------------
// PTX helpers
// ---------------------------------------------------------------------------
__device__ __forceinline__ uint32_t s2u(const void* p) {
    uint32_t a;
    asm("{ .reg .u64 t; cvta.to.shared.u64 t, %1; cvt.u32.u64 %0, t; }"
        : "=r"(a) : "l"(p));
    return a;
}
#define LDSM_X4(r0,r1,r2,r3,addr) \
    asm volatile("ldmatrix.sync.aligned.m8n8.x4.shared.b16 {%0,%1,%2,%3}, [%4];" \
        : "=r"(r0),"=r"(r1),"=r"(r2),"=r"(r3) : "r"(addr))

#define MMA_F16(c0,c1,c2,c3,a0,a1,a2,a3,b0,b1) \
    asm volatile("mma.sync.aligned.m16n8k16.row.col.f32.f16.f16.f32 " \
        "{%0,%1,%2,%3},{%4,%5,%6,%7},{%8,%9},{%0,%1,%2,%3};" \
        : "+f"(c0),"+f"(c1),"+f"(c2),"+f"(c3) \
        : "r"(a0),"r"(a1),"r"(a2),"r"(a3),"r"(b0),"r"(b1))

__device__ __forceinline__ void cpa16(uint32_t dst, const void* src) {
    asm volatile("cp.async.cg.shared.global [%0], [%1], 16;"
                 :: "r"(dst), "l"(src));
}
#define CP_COMMIT() asm volatile("cp.async.commit_group;")
#define CP_WAIT1()  asm volatile("cp.async.wait_group 1;")
#define CP_WAIT0()  asm volatile("cp.async.wait_group 0;")

// smem: BK=64, LDK=72 (144B rows -> 8-row ldmatrix covers all banks,
// conflict-free). Stage: A 128 rows + B 128 rows.
#define LDK 72
#define ROWB (LDK*2)                   // 144 bytes per row
#define TILE128 (128*ROWB)             // 18432
#define OFF_A 0
#define OFF_B TILE128
#define STAGE_B (2*TILE128)            // 36864
#define SMEM_TOTAL (3*STAGE_B)         // 110592 -> 2 CTAs/SM

// ---------------------------------------------------------------------------
// convert: f32 -> fp16
// ---------------------------------------------------------------------------
__device__ __forceinline__ unsigned short hfu(__half h) {
    return *reinterpret_cast<unsigned short*>(&h);
}
__global__ void conv_f16(const float* __restrict__ s,
                         __half* __restrict__ hi, int n4)
{
    int i = blockIdx.x * blockDim.x + threadIdx.x;
    if (i >= n4) return;
    float4 v = ((const float4*)s)[i];
    __half hx = __float2half_rn(v.x), hy = __float2half_rn(v.y);
    __half hz = __float2half_rn(v.z), hw = __float2half_rn(v.w);
    uint2 H;
    H.x = (unsigned)hfu(hx) | ((unsigned)hfu(hy) << 16);
    H.y = (unsigned)hfu(hz) | ((unsigned)hfu(hw) << 16);
    ((uint2*)hi)[i] = H;
}

// ---------------------------------------------------------------------------
// MMA consume for one BK=64 stage (4 ks-steps, barrier-free run).
// Warp tile 32m x 64n (2 m-frags x 8 n-frags).
// ---------------------------------------------------------------------------
__device__ __forceinline__ void mma_stage(uint32_t bb, int lane, int wm, int wn,
                                          float acc[2][8][4])
{
    #pragma unroll
    for (int ks = 0; ks < 4; ks++) {
        int kk = ks * 16;
        unsigned aH[2][4];
        {
            int ar = lane & 15;
            int ac = kk + 8 * (lane >> 4);
            #pragma unroll
            for (int mi = 0; mi < 2; mi++) {
                unsigned off = (wm + mi*16 + ar) * ROWB + ac * 2;
                LDSM_X4(aH[mi][0],aH[mi][1],aH[mi][2],aH[mi][3], bb + OFF_A + off);
            }
        }
        unsigned bH[8][2];
        {
            int r  = lane & 7;
            int kc = kk + ((lane >> 3) & 1) * 8;
            int n8 = (lane >> 4) ? 8 : 0;
            #pragma unroll
            for (int p = 0; p < 4; p++) {
                unsigned off = (wn + p*16 + n8 + r) * ROWB + kc * 2;
                LDSM_X4(bH[2*p][0],bH[2*p][1],bH[2*p+1][0],bH[2*p+1][1],
                        bb + OFF_B + off);
            }
        }
        #pragma unroll
        for (int mi = 0; mi < 2; mi++)
            #pragma unroll
            for (int ni = 0; ni < 8; ni++) {
                float* c = acc[mi][ni];
                MMA_F16(c[0],c[1],c[2],c[3],
                        aH[mi][0],aH[mi][1],aH[mi][2],aH[mi][3],
                        bH[ni][0],bH[ni][1]);
            }
    }
}

// ---------------------------------------------------------------------------
// K1: gemm1 (x @ W_in^T) + activation epilogue. Block 128m x 128col, K=512.
// Col j -> channel ch0+(j>>1); j&1: 0=hidden W row, 1=gate W row.
// Warps: 4 m-groups x 2 n-groups, warp tile 32x64. 3-stage BK=64, 1 sync/iter.
// ---------------------------------------------------------------------------
__global__ __launch_bounds__(256, 2)
void gemm1_tc(const float* __restrict__ bin)
{
    extern __shared__ char smem[];
    uint32_t su = s2u(smem);
    const int tid = threadIdx.x;
    const int lane = tid & 31;
    const int warp = tid >> 5;
    const int wm = (warp >> 1) * 32;
    const int wn = (warp & 1) * 64;
    const int m0 = blockIdx.x * 128;
    const int ch0 = blockIdx.y * 64;
    const int NC = Dq / 64;   // 8

    float acc[2][8][4];
    #pragma unroll
    for (int i = 0; i < 2; i++)
        #pragma unroll
        for (int j = 0; j < 8; j++)
            #pragma unroll
            for (int q = 0; q < 4; q++) acc[i][j][q] = 0.f;

    auto stage = [&](int c) {
        uint32_t bb = su + (c % 3) * STAGE_B;
        int k0 = c * 64;
        #pragma unroll
        for (int i = 0; i < 4; i++) {
            int id = tid + 256 * i;
            int row = id >> 3, c16 = id & 7;
            uint32_t off = (uint32_t)(row * ROWB + c16 * 16);
            size_t ai = (size_t)(m0 + row) * Dq + k0 + c16 * 8;
            cpa16(bb + OFF_A + off, g_xh + ai);
            int wrow = (row & 1) ? (Hq + ch0 + (row >> 1)) : (ch0 + (row >> 1));
            size_t bi = (size_t)wrow * Dq + k0 + c16 * 8;
            cpa16(bb + OFF_B + off, g_wih + bi);
        }
        CP_COMMIT();
    };

    stage(0); stage(1);
    for (int c = 0; c < NC; c++) {
        if (c + 1 < NC) { CP_WAIT1(); } else { CP_WAIT0(); }
        __syncthreads();
        if (c + 2 < NC) stage(c + 2);
        mma_stage(su + (c % 3) * STAGE_B, lane, wm, wn, acc);
    }

    // epilogue: activations -> packed half2 (c, zg)
    #pragma unroll
    for (int ni = 0; ni < 8; ni++) {
        int nloc = wn + ni*8 + 2*(lane & 3);
        int ch = ch0 + (nloc >> 1);
        float bh = bin[ch], bg = bin[Hq + ch];
        #pragma unroll
        for (int mi = 0; mi < 2; mi++) {
            float* c = acc[mi][ni];
            #pragma unroll
            for (int half = 0; half < 2; half++) {
                int row = m0 + wm + mi*16 + (lane >> 2) + half*8;
                float hid = c[2*half]   + bh;
                float gat = c[2*half+1] + bg;
                float z  = 1.f/(1.f + __expf(-gat));
                float cc = 1.f - z;
                float gt = (hid >= 0.f) ? (hid + 0.5f)
                                        : (1.f/(1.f + __expf(-hid)));
                g_cz[(size_t)row*Hq + ch] = __floats2half2_rn(cc, z * gt);
            }
        }
    }
}

// ---------------------------------------------------------------------------
// K2-K4: chunked scan (reads packed half2)
// ---------------------------------------------------------------------------
__global__ void scan_chunks()
{
    int h = blockIdx.x*256 + threadIdx.x;
    int chunk = blockIdx.y, b = blockIdx.z;
    size_t base = ((size_t)b*Lq + (size_t)chunk*CLEN)*Hq + h;
    float A = 1.f, Bv = 0.f;
    #pragma unroll 8
    for (int t = 0; t < CLEN; t++) {
        float2 v = __half22float2(g_cz[base]);
        Bv = v.x*Bv + v.y;
        A *= v.x;
        base += Hq;
    }
    size_t o = ((size_t)b*NCHUNK + chunk)*Hq + h;
    g_A[o] = A; g_Bc[o] = Bv;
}

__global__ void scan_tops()
{
    int g = blockIdx.x*256 + threadIdx.x;
    int b = g >> 10, hh = g & 1023;
    float hs = 0.f;
    size_t o = ((size_t)b*NCHUNK)*Hq + hh;
    for (int i = 0; i < NCHUNK; i++) {
        g_hs[o] = hs;
        hs = g_A[o]*hs + g_Bc[o];
        o += Hq;
    }
}

__global__ void scan_apply()
{
    int h = blockIdx.x*256 + threadIdx.x;
    int chunk = blockIdx.y, b = blockIdx.z;
    float hs = g_hs[((size_t)b*NCHUNK + chunk)*Hq + h];
    size_t base = ((size_t)b*Lq + (size_t)chunk*CLEN)*Hq + h;
    #pragma unroll 8
    for (int t = 0; t < CLEN; t++) {
        float2 v = __half22float2(g_cz[base]);
        hs = v.x*hs + v.y;
        g_hh[base] = __float2half_rn(hs);
        base += Hq;
    }
}

// ---------------------------------------------------------------------------
// K5: gemm2 (h @ W_out^T + b_out). Block 128m x 128n, K=1024, BK=64.
// ---------------------------------------------------------------------------
__global__ __launch_bounds__(256, 2)
void gemm2_tc(const float* __restrict__ bout, float* __restrict__ Out)
{
    extern __shared__ char smem[];
    uint32_t su = s2u(smem);
    const int tid = threadIdx.x;
    const int lane = tid & 31;
    const int warp = tid >> 5;
    const int wm = (warp >> 1) * 32;
    const int wn = (warp & 1) * 64;
    const int m0 = blockIdx.x * 128;
    const int n0 = blockIdx.y * 128;
    const int NC = Hq / 64;   // 16

    float acc[2][8][4];
    #pragma unroll
    for (int i = 0; i < 2; i++)
        #pragma unroll
        for (int j = 0; j < 8; j++)
            #pragma unroll
            for (int q = 0; q < 4; q++) acc[i][j][q] = 0.f;

    auto stage = [&](int c) {
        uint32_t bb = su + (c % 3) * STAGE_B;
        int k0 = c * 64;
        #pragma unroll
        for (int i = 0; i < 4; i++) {
            int id = tid + 256 * i;
            int row = id >> 3, c16 = id & 7;
            uint32_t off = (uint32_t)(row * ROWB + c16 * 16);
            size_t ai = (size_t)(m0 + row) * Hq + k0 + c16 * 8;
            cpa16(bb + OFF_A + off, g_hh + ai);
            size_t bi = (size_t)(n0 + row) * Hq + k0 + c16 * 8;
            cpa16(bb + OFF_B + off, g_woh + bi);
        }
        CP_COMMIT();
    };

    stage(0); stage(1);
    for (int c = 0; c < NC; c++) {
        if (c + 1 < NC) { CP_WAIT1(); } else { CP_WAIT0(); }
        __syncthreads();
        if (c + 2 < NC) stage(c + 2);
        mma_stage(su + (c % 3) * STAGE_B, lane, wm, wn, acc);
    }

    #pragma unroll
    for (int ni = 0; ni < 8; ni++) {
        int nd = n0 + wn + ni*8 + 2*(lane & 3);
        float b0 = bout[nd], b1 = bout[nd+1];
        #pragma unroll
        for (int mi = 0; mi < 2; mi++) {
            float* c = acc[mi][ni];
            #pragma unroll
            for (int half = 0; half < 2; half++) {
                int row = m0 + wm + mi*16 + (lane >> 2) + half*8;
                float2 o;
                o.x = c[2*half]   + b0;
                o.y = c[2*half+1] + b1;
                *(float2*)(Out + (size_t)row*Dq + nd) = o;
            }
        }
    }
}

// ---------------------------------------------------------------------------
extern "C" void kernel_launch(void* const* d_in, const int* in_sizes, int n_in,
                              void* d_out, int out_size)
{
    const float *x = nullptr, *win = nullptr, *bin = nullptr,
                *wout = nullptr, *bout = nullptr;
    for (int i = 0; i < n_in; i++) {
        switch (in_sizes[i]) {
            case Bq*Lq*Dq: x    = (const float*)d_in[i]; break;
            case 2*Hq*Dq:  win  = (const float*)d_in[i]; break;
            case 2*Hq:     bin  = (const float*)d_in[i]; break;
            case Dq*Hq:    wout = (const float*)d_in[i]; break;
            case Dq:       bout = (const float*)d_in[i]; break;
        }
    }
    float* out = (float*)d_out;

    static bool attr_done = false;
    if (!attr_done) {
        cudaFuncSetAttribute(gemm1_tc, cudaFuncAttributeMaxDynamicSharedMemorySize, SMEM_TOTAL);
        cudaFuncSetAttribute(gemm2_tc, cudaFuncAttributeMaxDynamicSharedMemorySize, SMEM_TOTAL);
        attr_done = true;
    }

    __half *xh, *wih, *woh;
    cudaGetSymbolAddress((void**)&xh,  g_xh);
    cudaGetSymbolAddress((void**)&wih, g_wih);
    cudaGetSymbolAddress((void**)&woh, g_woh);

    conv_f16<<<(Mq*Dq/4 + 255)/256, 256>>>(x, xh, Mq*Dq/4);
    conv_f16<<<(2*Hq*Dq/4 + 255)/256, 256>>>(win, wih, 2*Hq*Dq/4);
    conv_f16<<<(Dq*Hq/4 + 255)/256, 256>>>(wout, woh, Dq*Hq/4);

    gemm1_tc   <<<dim3(Mq/128, 2*Hq/128), 256, SMEM_TOTAL>>>(bin);
    scan_chunks<<<dim3(Hq/256, NCHUNK, Bq), 256>>>();
    scan_tops  <<<16, 256>>>();
    scan_apply <<<dim3(Hq/256, NCHUNK, Bq), 256>>>();
    gemm2_tc   <<<dim3(Mq/128, Dq/128), 256, SMEM_TOTAL>>>(bout, out);
}